// round 6
// baseline (speedup 1.0000x reference)
#include <cuda_runtime.h>
#include <cuda_fp16.h>
#include <cstdint>

// ---------------------------------------------------------------------------
// Problem constants
// ---------------------------------------------------------------------------
#define NTOK 8192
#define INF  1024
#define OUTF 1024
#define GS   8
#define KDIM (INF * 9)          // 9216 = silu + 8 laplacian features

static __device__ __align__(256) __half g_phi[(size_t)NTOK * KDIM];   // 151 MB
static __device__ __align__(256) __half g_w[(size_t)OUTF * KDIM];     // 18.9 MB

// ---------------------------------------------------------------------------
// prep_w: fold base + spline*scaler into combined fp16 weights
// ---------------------------------------------------------------------------
__global__ void prep_w_kernel(const float* __restrict__ bw,
                              const float* __restrict__ sw,
                              const float* __restrict__ sc) {
    int idx = blockIdx.x * blockDim.x + threadIdx.x;
    if (idx >= OUTF * INF) return;
    int o = idx / INF;
    int i = idx - o * INF;
    size_t base = (size_t)o * KDIM + i;
    float scaler = sc[idx];
    g_w[base] = __float2half(bw[idx]);
    #pragma unroll
    for (int g = 0; g < GS; g++)
        g_w[base + (size_t)(1 + g) * INF] = __float2half(sw[(size_t)idx * GS + g] * scaler);
}

// ---------------------------------------------------------------------------
// prep_phi v2 (kept from R5): MUFU-free exp via polynomial exp2.
// exp(-|x-g|) = min(e^x * e^-g, e^-x * e^g); silu via Newton reciprocal.
// ---------------------------------------------------------------------------
__device__ __forceinline__ void exp_pm(float xv, float& E, float& R) {
    const float L2E = 1.4426950408889634f;
    float s = xv * L2E;
    float k = s + 12582912.0f;                    // round-to-nearest magic
    int   n = __float_as_int(k) - 0x4B400000;
    float f = s - (k - 12582912.0f);              // f in [-0.5, 0.5]
    float p = 1.33335581e-3f;
    p = fmaf(p, f, 9.61812910e-3f);
    p = fmaf(p, f, 5.55041087e-2f);
    p = fmaf(p, f, 2.40226507e-1f);
    p = fmaf(p, f, 6.93147181e-1f);
    p = fmaf(p, f, 1.0f);
    float nf = -f;
    float q = 1.33335581e-3f;
    q = fmaf(q, nf, 9.61812910e-3f);
    q = fmaf(q, nf, 5.55041087e-2f);
    q = fmaf(q, nf, 2.40226507e-1f);
    q = fmaf(q, nf, 6.93147181e-1f);
    q = fmaf(q, nf, 1.0f);
    E = p * __int_as_float((127 + n) << 23);
    R = q * __int_as_float((127 - n) << 23);
}

__device__ __forceinline__ float fast_sigmoid_from_R(float R) {
    float d = 1.0f + R;
    float y = __int_as_float(0x7EF477D5 - __float_as_int(d));
    y = y * (2.0f - d * y);
    y = y * (2.0f - d * y);
    y = y * (2.0f - d * y);
    return y;
}

__global__ void __launch_bounds__(256) prep_phi2_kernel(const float* __restrict__ x,
                                                        const float* __restrict__ gridp) {
    const int tid = threadIdx.x;
    const int ih = blockIdx.x & 1;
    const int nc = blockIdx.x >> 1;
    const int ip = ih * 256 + tid;
    const int i0 = 2 * ip;
    const int n0 = nc * 64;

    float cE[2][GS], cR[2][GS];
    #pragma unroll
    for (int e = 0; e < 2; e++)
        #pragma unroll
        for (int g = 0; g < GS; g++) {
            float gv = gridp[(i0 + e) * GS + g];
            cE[e][g] = __expf(-gv);
            cR[e][g] = __expf(gv);
        }

    for (int n = n0; n < n0 + 64; n++) {
        float2 xv = *reinterpret_cast<const float2*>(x + (size_t)n * INF + i0);
        float E0, R0, E1, R1;
        exp_pm(xv.x, E0, R0);
        exp_pm(xv.y, E1, R1);

        float sil0 = xv.x * fast_sigmoid_from_R(R0);
        float sil1 = xv.y * fast_sigmoid_from_R(R1);

        __half* base = g_phi + (size_t)n * KDIM + i0;
        *reinterpret_cast<__half2*>(base) = __floats2half2_rn(sil0, sil1);
        #pragma unroll
        for (int g = 0; g < GS; g++) {
            float v0 = fminf(E0 * cE[0][g], R0 * cR[0][g]);
            float v1 = fminf(E1 * cE[1][g], R1 * cR[1][g]);
            *reinterpret_cast<__half2*>(base + (size_t)(1 + g) * INF) =
                __floats2half2_rn(v0, v1);
        }
    }
}

// ---------------------------------------------------------------------------
// fp16 GEMM — EXACT R4 version (proven fast): mma m16n8k16, CTA 128x128x64,
// 256 thr, warps 4(m) x 2(n) warp tile 32x64, 3-stage cp.async, 2 CTAs/SM.
// ---------------------------------------------------------------------------
#define BM 128
#define BN 128
#define BKH 64
#define STAGES 3
#define A_BYTES (BM * 128)
#define B_BYTES (BN * 128)
#define STAGE_BYTES (A_BYTES + B_BYTES)          // 32 KB
#define SMEM_BYTES (STAGES * STAGE_BYTES)        // 96 KB
#define KT (KDIM / BKH)                          // 144

__device__ __forceinline__ void cp_async16(uint32_t smem_addr, const void* gptr) {
    asm volatile("cp.async.cg.shared.global [%0], [%1], 16;\n" :: "r"(smem_addr), "l"(gptr));
}
__device__ __forceinline__ uint32_t smem_u32(const void* p) {
    uint32_t a;
    asm("{ .reg .u64 t; cvta.to.shared.u64 t, %1; cvt.u32.u64 %0, t; }" : "=r"(a) : "l"(p));
    return a;
}
__device__ __forceinline__ uint32_t lds32(uint32_t addr) {
    uint32_t v;
    asm volatile("ld.shared.b32 %0, [%1];" : "=r"(v) : "r"(addr));
    return v;
}
__device__ __forceinline__ void mma_f16(float c[4], const uint32_t a[4], const uint32_t b[2]) {
    asm volatile(
        "mma.sync.aligned.m16n8k16.row.col.f32.f16.f16.f32 "
        "{%0,%1,%2,%3}, {%4,%5,%6,%7}, {%8,%9}, {%0,%1,%2,%3};\n"
        : "+f"(c[0]), "+f"(c[1]), "+f"(c[2]), "+f"(c[3])
        : "r"(a[0]), "r"(a[1]), "r"(a[2]), "r"(a[3]), "r"(b[0]), "r"(b[1]));
}
__device__ __forceinline__ uint32_t swz(int row, int chunk) {
    return (uint32_t)(row * 128 + ((chunk ^ (row & 7)) << 4));
}

__global__ void __launch_bounds__(256, 2) gemm_f16_kernel(float* __restrict__ C) {
    extern __shared__ __align__(1024) char smem[];
    const uint32_t sb = smem_u32(smem);

    const int tid  = threadIdx.x;
    const int warp = tid >> 5;
    const int lane = tid & 31;
    const int g    = lane >> 2;
    const int t4   = lane & 3;
    const int wm   = (warp & 3) * 32;
    const int wn   = (warp >> 2) * 64;

    const int m0 = blockIdx.y * BM;
    const int n0 = blockIdx.x * BN;

    const int crow = tid >> 1;
    const int cch0 = (tid & 1) * 4;
    const __half* Ag = g_phi + (size_t)(m0 + crow) * KDIM + cch0 * 8;
    const __half* Bg = g_w   + (size_t)(n0 + crow) * KDIM + cch0 * 8;
    uint32_t Asw[4], Bsw[4];
    #pragma unroll
    for (int j = 0; j < 4; j++) {
        Asw[j] = sb + swz(crow, cch0 + j);
        Bsw[j] = sb + A_BYTES + swz(crow, cch0 + j);
    }

    float acc[2][8][4];
    #pragma unroll
    for (int mi = 0; mi < 2; mi++)
        #pragma unroll
        for (int ni = 0; ni < 8; ni++)
            #pragma unroll
            for (int r = 0; r < 4; r++) acc[mi][ni][r] = 0.0f;

    #pragma unroll
    for (int s = 0; s < 2; s++) {
        const uint32_t so = s * STAGE_BYTES;
        const int ko = s * BKH;
        #pragma unroll
        for (int j = 0; j < 4; j++) {
            cp_async16(Asw[j] + so, Ag + ko + j * 8);
            cp_async16(Bsw[j] + so, Bg + ko + j * 8);
        }
        asm volatile("cp.async.commit_group;\n");
    }

    const uint32_t aoff = t4 * 4;

    for (int kt = 0; kt < KT; kt++) {
        if (kt < KT - 1) asm volatile("cp.async.wait_group 1;\n");
        else             asm volatile("cp.async.wait_group 0;\n");
        __syncthreads();

        if (kt + 2 < KT) {
            const uint32_t so = ((kt + 2) % STAGES) * STAGE_BYTES;
            const int ko = (kt + 2) * BKH;
            #pragma unroll
            for (int j = 0; j < 4; j++) {
                cp_async16(Asw[j] + so, Ag + ko + j * 8);
                cp_async16(Bsw[j] + so, Bg + ko + j * 8);
            }
            asm volatile("cp.async.commit_group;\n");
        }

        const uint32_t as = sb + (kt % STAGES) * STAGE_BYTES;
        const uint32_t bs = as + A_BYTES;

        #pragma unroll
        for (int ks = 0; ks < 4; ks++) {
            const int ch = 2 * ks;
            uint32_t a[2][4], b[8][2];
            #pragma unroll
            for (int mi = 0; mi < 2; mi++) {
                const int r = wm + mi * 16 + g;
                a[mi][0] = lds32(as + swz(r,     ch)     + aoff);
                a[mi][1] = lds32(as + swz(r + 8, ch)     + aoff);
                a[mi][2] = lds32(as + swz(r,     ch + 1) + aoff);
                a[mi][3] = lds32(as + swz(r + 8, ch + 1) + aoff);
            }
            #pragma unroll
            for (int ni = 0; ni < 8; ni++) {
                const int rn = wn + ni * 8 + g;
                b[ni][0] = lds32(bs + swz(rn, ch)     + aoff);
                b[ni][1] = lds32(bs + swz(rn, ch + 1) + aoff);
            }
            #pragma unroll
            for (int mi = 0; mi < 2; mi++)
                #pragma unroll
                for (int ni = 0; ni < 8; ni++)
                    mma_f16(acc[mi][ni], a[mi], b[ni]);
        }
    }

    #pragma unroll
    for (int mi = 0; mi < 2; mi++) {
        const int row = m0 + wm + mi * 16 + g;
        #pragma unroll
        for (int ni = 0; ni < 8; ni++) {
            const int col = n0 + wn + ni * 8 + t4 * 2;
            *reinterpret_cast<float2*>(C + (size_t)row * OUTF + col) =
                make_float2(acc[mi][ni][0], acc[mi][ni][1]);
            *reinterpret_cast<float2*>(C + (size_t)(row + 8) * OUTF + col) =
                make_float2(acc[mi][ni][2], acc[mi][ni][3]);
        }
    }
}

// ---------------------------------------------------------------------------
extern "C" void kernel_launch(void* const* d_in, const int* in_sizes, int n_in,
                              void* d_out, int out_size) {
    const float* x    = (const float*)d_in[0];   // (8192, 1024)
    const float* bw   = (const float*)d_in[1];   // (1024, 1024)
    const float* sw   = (const float*)d_in[2];   // (1024, 1024, 8)
    const float* sc   = (const float*)d_in[3];   // (1024, 1024)
    const float* grid = (const float*)d_in[4];   // (1024, 8)
    float* out = (float*)d_out;                  // (8192, 1024)

    (void)in_sizes; (void)n_in; (void)out_size;

    cudaFuncSetAttribute(gemm_f16_kernel,
                         cudaFuncAttributeMaxDynamicSharedMemorySize, SMEM_BYTES);

    prep_w_kernel<<<(OUTF * INF + 255) / 256, 256>>>(bw, sw, sc);
    prep_phi2_kernel<<<256, 256>>>(x, grid);

    dim3 gdim(OUTF / BN, NTOK / BM);   // (8, 64) = 512 CTAs
    gemm_f16_kernel<<<gdim, 256, SMEM_BYTES>>>(out);
}

// round 7
// speedup vs baseline: 1.7533x; 1.7533x over previous
#include <cuda_runtime.h>
#include <cuda_fp16.h>
#include <cstdint>

// ---------------------------------------------------------------------------
// Problem constants
// ---------------------------------------------------------------------------
#define NTOK 8192
#define INF  1024
#define OUTF 1024
#define GS   8
#define KDIM (INF * 9)          // 9216 = silu + 8 laplacian features

static __device__ __align__(256) __half g_phi[(size_t)NTOK * KDIM];   // 151 MB
static __device__ __align__(256) __half g_w[(size_t)OUTF * KDIM];     // 18.9 MB

// ---------------------------------------------------------------------------
// prep_w: fold base + spline*scaler into combined fp16 weights
// ---------------------------------------------------------------------------
__global__ void prep_w_kernel(const float* __restrict__ bw,
                              const float* __restrict__ sw,
                              const float* __restrict__ sc) {
    int idx = blockIdx.x * blockDim.x + threadIdx.x;
    if (idx >= OUTF * INF) return;
    int o = idx / INF;
    int i = idx - o * INF;
    size_t base = (size_t)o * KDIM + i;
    float scaler = sc[idx];
    g_w[base] = __float2half(bw[idx]);
    #pragma unroll
    for (int g = 0; g < GS; g++)
        g_w[base + (size_t)(1 + g) * INF] = __float2half(sw[(size_t)idx * GS + g] * scaler);
}

// ---------------------------------------------------------------------------
// prep_phi v2.1: MUFU-free poly exp2; 512 blocks x 32 tokens for balance.
// exp(-|x-g|) = min(e^x * e^-g, e^-x * e^g); silu via Newton reciprocal.
// ---------------------------------------------------------------------------
__device__ __forceinline__ void exp_pm(float xv, float& E, float& R) {
    const float L2E = 1.4426950408889634f;
    float s = xv * L2E;
    float k = s + 12582912.0f;                    // round-to-nearest magic
    int   n = __float_as_int(k) - 0x4B400000;
    float f = s - (k - 12582912.0f);              // f in [-0.5, 0.5]
    float p = 1.33335581e-3f;
    p = fmaf(p, f, 9.61812910e-3f);
    p = fmaf(p, f, 5.55041087e-2f);
    p = fmaf(p, f, 2.40226507e-1f);
    p = fmaf(p, f, 6.93147181e-1f);
    p = fmaf(p, f, 1.0f);
    float nf = -f;
    float q = 1.33335581e-3f;
    q = fmaf(q, nf, 9.61812910e-3f);
    q = fmaf(q, nf, 5.55041087e-2f);
    q = fmaf(q, nf, 2.40226507e-1f);
    q = fmaf(q, nf, 6.93147181e-1f);
    q = fmaf(q, nf, 1.0f);
    E = p * __int_as_float((127 + n) << 23);
    R = q * __int_as_float((127 - n) << 23);
}

__device__ __forceinline__ float fast_sigmoid_from_R(float R) {
    float d = 1.0f + R;
    float y = __int_as_float(0x7EF477D5 - __float_as_int(d));
    y = y * (2.0f - d * y);
    y = y * (2.0f - d * y);
    y = y * (2.0f - d * y);
    return y;
}

__global__ void __launch_bounds__(256) prep_phi2_kernel(const float* __restrict__ x,
                                                        const float* __restrict__ gridp) {
    const int tid = threadIdx.x;
    const int ih = blockIdx.x & 1;                // i-half
    const int nc = blockIdx.x >> 1;               // 0..255 token chunk
    const int i0 = 2 * (ih * 256 + tid);
    const int n0 = nc * 32;

    float cE[2][GS], cR[2][GS];
    #pragma unroll
    for (int e = 0; e < 2; e++)
        #pragma unroll
        for (int g = 0; g < GS; g++) {
            float gv = gridp[(i0 + e) * GS + g];
            cE[e][g] = __expf(-gv);
            cR[e][g] = __expf(gv);
        }

    for (int n = n0; n < n0 + 32; n++) {
        float2 xv = *reinterpret_cast<const float2*>(x + (size_t)n * INF + i0);
        float E0, R0, E1, R1;
        exp_pm(xv.x, E0, R0);
        exp_pm(xv.y, E1, R1);

        float sil0 = xv.x * fast_sigmoid_from_R(R0);
        float sil1 = xv.y * fast_sigmoid_from_R(R1);

        __half* base = g_phi + (size_t)n * KDIM + i0;
        *reinterpret_cast<__half2*>(base) = __floats2half2_rn(sil0, sil1);
        #pragma unroll
        for (int g = 0; g < GS; g++) {
            float v0 = fminf(E0 * cE[0][g], R0 * cR[0][g]);
            float v1 = fminf(E1 * cE[1][g], R1 * cR[1][g]);
            *reinterpret_cast<__half2*>(base + (size_t)(1 + g) * INF) =
                __floats2half2_rn(v0, v1);
        }
    }
}

// ---------------------------------------------------------------------------
// fp16 GEMM v2.1: C = Phi @ W^T, mma m16n8k16 + ldmatrix.x4.
// CTA 128(M) x 256(N) x 64(Kh), 256 thr, 8 warps (2m x 4n), warp 64x64.
// 4-stage cp.async (192 KB, 1 CTA/SM), wait_group 2 with exact tail drain.
// ---------------------------------------------------------------------------
#define BM 128
#define BN 256
#define BKH 64
#define STAGES 4
#define A_BYTES (BM * 128)                 // 16 KB
#define B_BYTES (BN * 128)                 // 32 KB
#define STAGE_BYTES (A_BYTES + B_BYTES)    // 48 KB
#define SMEM_BYTES (STAGES * STAGE_BYTES)  // 192 KB
#define KT (KDIM / BKH)                    // 144

__device__ __forceinline__ void cp_async16(uint32_t smem_addr, const void* gptr) {
    asm volatile("cp.async.cg.shared.global [%0], [%1], 16;\n" :: "r"(smem_addr), "l"(gptr));
}
__device__ __forceinline__ uint32_t smem_u32(const void* p) {
    uint32_t a;
    asm("{ .reg .u64 t; cvta.to.shared.u64 t, %1; cvt.u32.u64 %0, t; }" : "=r"(a) : "l"(p));
    return a;
}
__device__ __forceinline__ void ldsm4(uint32_t r[4], uint32_t addr) {
    asm volatile("ldmatrix.sync.aligned.m8n8.x4.shared.b16 {%0,%1,%2,%3}, [%4];"
                 : "=r"(r[0]), "=r"(r[1]), "=r"(r[2]), "=r"(r[3]) : "r"(addr));
}
__device__ __forceinline__ void mma_f16(float c[4], const uint32_t a[4],
                                        uint32_t b0, uint32_t b1) {
    asm volatile(
        "mma.sync.aligned.m16n8k16.row.col.f32.f16.f16.f32 "
        "{%0,%1,%2,%3}, {%4,%5,%6,%7}, {%8,%9}, {%0,%1,%2,%3};\n"
        : "+f"(c[0]), "+f"(c[1]), "+f"(c[2]), "+f"(c[3])
        : "r"(a[0]), "r"(a[1]), "r"(a[2]), "r"(a[3]), "r"(b0), "r"(b1));
}
__device__ __forceinline__ uint32_t swz(int row, int chunk) {
    return (uint32_t)(row * 128 + ((chunk ^ (row & 7)) << 4));
}

__global__ void __launch_bounds__(256, 1) gemm_f16_kernel(float* __restrict__ C) {
    extern __shared__ __align__(1024) char smem[];
    const uint32_t sb = smem_u32(smem);

    const int tid  = threadIdx.x;
    const int warp = tid >> 5;
    const int lane = tid & 31;
    const int wm = (warp & 1) * 64;
    const int wn = (warp >> 1) * 64;

    const int m0 = blockIdx.y * BM;
    const int n0 = blockIdx.x * BN;

    // ---- producer addressing ----
    const int crow = tid >> 1;
    const int cch0 = (tid & 1) * 4;
    const __half* Ag  = g_phi + (size_t)(m0 + crow) * KDIM + cch0 * 8;
    const __half* Bg0 = g_w   + (size_t)(n0 + crow) * KDIM + cch0 * 8;
    const __half* Bg1 = g_w   + (size_t)(n0 + 128 + crow) * KDIM + cch0 * 8;
    uint32_t Ad[4], Bd0[4], Bd1[4];
    #pragma unroll
    for (int j = 0; j < 4; j++) {
        Ad[j]  = sb + swz(crow, cch0 + j);
        Bd0[j] = sb + A_BYTES + swz(crow, cch0 + j);
        Bd1[j] = sb + A_BYTES + 128 * 128 + swz(crow, cch0 + j);
    }

    // ---- fragment address bases ----
    const int lA  = lane & 15;
    const int cA  = lane >> 4;
    const int lB  = (lane & 7) + ((lane >> 4) << 3);
    const int cB  = (lane >> 3) & 1;
    uint32_t aRow[4]; int a7[4];
    uint32_t bRow[4]; int b7[4];
    #pragma unroll
    for (int mi = 0; mi < 4; mi++) {
        int r = wm + mi * 16 + lA;
        aRow[mi] = (uint32_t)(r * 128);
        a7[mi] = r & 7;
    }
    #pragma unroll
    for (int j = 0; j < 4; j++) {
        int r = wn + j * 16 + lB;
        bRow[j] = (uint32_t)(r * 128);
        b7[j] = r & 7;
    }

    float acc[4][8][4];
    #pragma unroll
    for (int mi = 0; mi < 4; mi++)
        #pragma unroll
        for (int ni = 0; ni < 8; ni++)
            #pragma unroll
            for (int r = 0; r < 4; r++) acc[mi][ni][r] = 0.0f;

    // ---- prologue: stages 0..2 ----
    #pragma unroll
    for (int s = 0; s < 3; s++) {
        const uint32_t so = s * STAGE_BYTES;
        const int ko = s * BKH;
        #pragma unroll
        for (int j = 0; j < 4; j++) {
            cp_async16(Ad[j]  + so, Ag  + ko + j * 8);
            cp_async16(Bd0[j] + so, Bg0 + ko + j * 8);
            cp_async16(Bd1[j] + so, Bg1 + ko + j * 8);
        }
        asm volatile("cp.async.commit_group;\n");
    }

    for (int kt = 0; kt < KT; kt++) {
        // drain so that stage kt is complete
        if (kt < KT - 2)       asm volatile("cp.async.wait_group 2;\n");
        else if (kt == KT - 2) asm volatile("cp.async.wait_group 1;\n");
        else                   asm volatile("cp.async.wait_group 0;\n");
        __syncthreads();

        if (kt + 3 < KT) {
            const uint32_t so = ((kt + 3) % STAGES) * STAGE_BYTES;
            const int ko = (kt + 3) * BKH;
            #pragma unroll
            for (int j = 0; j < 4; j++) {
                cp_async16(Ad[j]  + so, Ag  + ko + j * 8);
                cp_async16(Bd0[j] + so, Bg0 + ko + j * 8);
                cp_async16(Bd1[j] + so, Bg1 + ko + j * 8);
            }
            asm volatile("cp.async.commit_group;\n");
        }

        const uint32_t stA = sb + (kt % STAGES) * STAGE_BYTES;
        const uint32_t stB = stA + A_BYTES;

        #pragma unroll
        for (int ks = 0; ks < 4; ks++) {
            uint32_t a[4][4], b[4][4];
            const int ka = 2 * ks + cA;
            const int kb = 2 * ks + cB;
            #pragma unroll
            for (int mi = 0; mi < 4; mi++)
                ldsm4(a[mi], stA + aRow[mi] + (uint32_t)((ka ^ a7[mi]) << 4));
            #pragma unroll
            for (int j = 0; j < 4; j++)
                ldsm4(b[j], stB + bRow[j] + (uint32_t)((kb ^ b7[j]) << 4));
            #pragma unroll
            for (int mi = 0; mi < 4; mi++)
                #pragma unroll
                for (int ni = 0; ni < 8; ni++)
                    mma_f16(acc[mi][ni], a[mi], b[ni >> 1][2 * (ni & 1)],
                                                 b[ni >> 1][2 * (ni & 1) + 1]);
        }
    }

    // ---- epilogue ----
    const int g4 = lane >> 2;
    const int t4 = lane & 3;
    #pragma unroll
    for (int mi = 0; mi < 4; mi++) {
        const int row = m0 + wm + mi * 16 + g4;
        #pragma unroll
        for (int ni = 0; ni < 8; ni++) {
            const int col = n0 + wn + ni * 8 + t4 * 2;
            *reinterpret_cast<float2*>(C + (size_t)row * OUTF + col) =
                make_float2(acc[mi][ni][0], acc[mi][ni][1]);
            *reinterpret_cast<float2*>(C + (size_t)(row + 8) * OUTF + col) =
                make_float2(acc[mi][ni][2], acc[mi][ni][3]);
        }
    }
}

// ---------------------------------------------------------------------------
extern "C" void kernel_launch(void* const* d_in, const int* in_sizes, int n_in,
                              void* d_out, int out_size) {
    const float* x    = (const float*)d_in[0];   // (8192, 1024)
    const float* bw   = (const float*)d_in[1];   // (1024, 1024)
    const float* sw   = (const float*)d_in[2];   // (1024, 1024, 8)
    const float* sc   = (const float*)d_in[3];   // (1024, 1024)
    const float* grid = (const float*)d_in[4];   // (1024, 8)
    float* out = (float*)d_out;                  // (8192, 1024)

    (void)in_sizes; (void)n_in; (void)out_size;

    cudaFuncSetAttribute(gemm_f16_kernel,
                         cudaFuncAttributeMaxDynamicSharedMemorySize, SMEM_BYTES);

    prep_w_kernel<<<(OUTF * INF + 255) / 256, 256>>>(bw, sw, sc);
    prep_phi2_kernel<<<512, 256>>>(x, grid);     // 2 i-halves x 256 chunks of 32 tokens

    dim3 gdim(OUTF / BN, NTOK / BM);             // (4, 64) = 256 CTAs
    gemm_f16_kernel<<<gdim, 256, SMEM_BYTES>>>(out);
}

// round 8
// speedup vs baseline: 1.8323x; 1.0450x over previous
#include <cuda_runtime.h>
#include <cuda_fp16.h>
#include <cstdint>

// ---------------------------------------------------------------------------
// Problem constants
// ---------------------------------------------------------------------------
#define NTOK 8192
#define INF  1024
#define OUTF 1024
#define GS   8
#define KDIM (INF * 9)          // 9216 = silu + 8 laplacian features

static __device__ __align__(256) __half g_phi[(size_t)NTOK * KDIM];   // 151 MB
static __device__ __align__(256) __half g_w[(size_t)OUTF * KDIM];     // 18.9 MB

// ---------------------------------------------------------------------------
// prep_w: fold base + spline*scaler into combined fp16 weights
// ---------------------------------------------------------------------------
__global__ void prep_w_kernel(const float* __restrict__ bw,
                              const float* __restrict__ sw,
                              const float* __restrict__ sc) {
    int idx = blockIdx.x * blockDim.x + threadIdx.x;
    if (idx >= OUTF * INF) return;
    int o = idx / INF;
    int i = idx - o * INF;
    size_t base = (size_t)o * KDIM + i;
    float scaler = sc[idx];
    g_w[base] = __float2half(bw[idx]);
    #pragma unroll
    for (int g = 0; g < GS; g++)
        g_w[base + (size_t)(1 + g) * INF] = __float2half(sw[(size_t)idx * GS + g] * scaler);
}

// ---------------------------------------------------------------------------
// prep_phi v2.1 (proven): MUFU-free poly exp2; 512 blocks x 32 tokens.
// ---------------------------------------------------------------------------
__device__ __forceinline__ void exp_pm(float xv, float& E, float& R) {
    const float L2E = 1.4426950408889634f;
    float s = xv * L2E;
    float k = s + 12582912.0f;
    int   n = __float_as_int(k) - 0x4B400000;
    float f = s - (k - 12582912.0f);
    float p = 1.33335581e-3f;
    p = fmaf(p, f, 9.61812910e-3f);
    p = fmaf(p, f, 5.55041087e-2f);
    p = fmaf(p, f, 2.40226507e-1f);
    p = fmaf(p, f, 6.93147181e-1f);
    p = fmaf(p, f, 1.0f);
    float nf = -f;
    float q = 1.33335581e-3f;
    q = fmaf(q, nf, 9.61812910e-3f);
    q = fmaf(q, nf, 5.55041087e-2f);
    q = fmaf(q, nf, 2.40226507e-1f);
    q = fmaf(q, nf, 6.93147181e-1f);
    q = fmaf(q, nf, 1.0f);
    E = p * __int_as_float((127 + n) << 23);
    R = q * __int_as_float((127 - n) << 23);
}

__device__ __forceinline__ float fast_sigmoid_from_R(float R) {
    float d = 1.0f + R;
    float y = __int_as_float(0x7EF477D5 - __float_as_int(d));
    y = y * (2.0f - d * y);
    y = y * (2.0f - d * y);
    y = y * (2.0f - d * y);
    return y;
}

__global__ void __launch_bounds__(256) prep_phi2_kernel(const float* __restrict__ x,
                                                        const float* __restrict__ gridp) {
    const int tid = threadIdx.x;
    const int ih = blockIdx.x & 1;
    const int nc = blockIdx.x >> 1;
    const int i0 = 2 * (ih * 256 + tid);
    const int n0 = nc * 32;

    float cE[2][GS], cR[2][GS];
    #pragma unroll
    for (int e = 0; e < 2; e++)
        #pragma unroll
        for (int g = 0; g < GS; g++) {
            float gv = gridp[(i0 + e) * GS + g];
            cE[e][g] = __expf(-gv);
            cR[e][g] = __expf(gv);
        }

    for (int n = n0; n < n0 + 32; n++) {
        float2 xv = *reinterpret_cast<const float2*>(x + (size_t)n * INF + i0);
        float E0, R0, E1, R1;
        exp_pm(xv.x, E0, R0);
        exp_pm(xv.y, E1, R1);

        float sil0 = xv.x * fast_sigmoid_from_R(R0);
        float sil1 = xv.y * fast_sigmoid_from_R(R1);

        __half* base = g_phi + (size_t)n * KDIM + i0;
        *reinterpret_cast<__half2*>(base) = __floats2half2_rn(sil0, sil1);
        #pragma unroll
        for (int g = 0; g < GS; g++) {
            float v0 = fminf(E0 * cE[0][g], R0 * cR[0][g]);
            float v1 = fminf(E1 * cE[1][g], R1 * cR[1][g]);
            *reinterpret_cast<__half2*>(base + (size_t)(1 + g) * INF) =
                __floats2half2_rn(v0, v1);
        }
    }
}

// ---------------------------------------------------------------------------
// fp16 GEMM v3: as R7 (CTA 128x256x64h, 8 warps, warp 64x64, 4-stage
// cp.async) + register double-buffered ldmatrix: frags for ks+1 are
// issued before the mma burst of ks, hiding LDSM latency.
// ---------------------------------------------------------------------------
#define BM 128
#define BN 256
#define BKH 64
#define STAGES 4
#define A_BYTES (BM * 128)                 // 16 KB
#define B_BYTES (BN * 128)                 // 32 KB
#define STAGE_BYTES (A_BYTES + B_BYTES)    // 48 KB
#define SMEM_BYTES (STAGES * STAGE_BYTES)  // 192 KB
#define KT (KDIM / BKH)                    // 144

__device__ __forceinline__ void cp_async16(uint32_t smem_addr, const void* gptr) {
    asm volatile("cp.async.cg.shared.global [%0], [%1], 16;\n" :: "r"(smem_addr), "l"(gptr));
}
__device__ __forceinline__ uint32_t smem_u32(const void* p) {
    uint32_t a;
    asm("{ .reg .u64 t; cvta.to.shared.u64 t, %1; cvt.u32.u64 %0, t; }" : "=r"(a) : "l"(p));
    return a;
}
__device__ __forceinline__ void ldsm4(uint32_t r[4], uint32_t addr) {
    asm volatile("ldmatrix.sync.aligned.m8n8.x4.shared.b16 {%0,%1,%2,%3}, [%4];"
                 : "=r"(r[0]), "=r"(r[1]), "=r"(r[2]), "=r"(r[3]) : "r"(addr));
}
__device__ __forceinline__ void mma_f16(float c[4], const uint32_t a[4],
                                        uint32_t b0, uint32_t b1) {
    asm volatile(
        "mma.sync.aligned.m16n8k16.row.col.f32.f16.f16.f32 "
        "{%0,%1,%2,%3}, {%4,%5,%6,%7}, {%8,%9}, {%0,%1,%2,%3};\n"
        : "+f"(c[0]), "+f"(c[1]), "+f"(c[2]), "+f"(c[3])
        : "r"(a[0]), "r"(a[1]), "r"(a[2]), "r"(a[3]), "r"(b0), "r"(b1));
}
__device__ __forceinline__ uint32_t swz(int row, int chunk) {
    return (uint32_t)(row * 128 + ((chunk ^ (row & 7)) << 4));
}

__global__ void __launch_bounds__(256, 1) gemm_f16_kernel(float* __restrict__ C) {
    extern __shared__ __align__(1024) char smem[];
    const uint32_t sb = smem_u32(smem);

    const int tid  = threadIdx.x;
    const int warp = tid >> 5;
    const int lane = tid & 31;
    const int wm = (warp & 1) * 64;
    const int wn = (warp >> 1) * 64;

    const int m0 = blockIdx.y * BM;
    const int n0 = blockIdx.x * BN;

    // ---- producer addressing ----
    const int crow = tid >> 1;
    const int cch0 = (tid & 1) * 4;
    const __half* Ag  = g_phi + (size_t)(m0 + crow) * KDIM + cch0 * 8;
    const __half* Bg0 = g_w   + (size_t)(n0 + crow) * KDIM + cch0 * 8;
    const __half* Bg1 = g_w   + (size_t)(n0 + 128 + crow) * KDIM + cch0 * 8;
    uint32_t Ad[4], Bd0[4], Bd1[4];
    #pragma unroll
    for (int j = 0; j < 4; j++) {
        Ad[j]  = sb + swz(crow, cch0 + j);
        Bd0[j] = sb + A_BYTES + swz(crow, cch0 + j);
        Bd1[j] = sb + A_BYTES + 128 * 128 + swz(crow, cch0 + j);
    }

    // ---- fragment address bases ----
    const int lA  = lane & 15;
    const int cA  = lane >> 4;
    const int lB  = (lane & 7) + ((lane >> 4) << 3);
    const int cB  = (lane >> 3) & 1;
    uint32_t aRow[4]; int a7[4];
    uint32_t bRow[4]; int b7[4];
    #pragma unroll
    for (int mi = 0; mi < 4; mi++) {
        int r = wm + mi * 16 + lA;
        aRow[mi] = (uint32_t)(r * 128);
        a7[mi] = r & 7;
    }
    #pragma unroll
    for (int j = 0; j < 4; j++) {
        int r = wn + j * 16 + lB;
        bRow[j] = (uint32_t)(r * 128);
        b7[j] = r & 7;
    }

    float acc[4][8][4];
    #pragma unroll
    for (int mi = 0; mi < 4; mi++)
        #pragma unroll
        for (int ni = 0; ni < 8; ni++)
            #pragma unroll
            for (int r = 0; r < 4; r++) acc[mi][ni][r] = 0.0f;

    // ---- prologue: stages 0..2 ----
    #pragma unroll
    for (int s = 0; s < 3; s++) {
        const uint32_t so = s * STAGE_BYTES;
        const int ko = s * BKH;
        #pragma unroll
        for (int j = 0; j < 4; j++) {
            cp_async16(Ad[j]  + so, Ag  + ko + j * 8);
            cp_async16(Bd0[j] + so, Bg0 + ko + j * 8);
            cp_async16(Bd1[j] + so, Bg1 + ko + j * 8);
        }
        asm volatile("cp.async.commit_group;\n");
    }

    for (int kt = 0; kt < KT; kt++) {
        if (kt < KT - 2)       asm volatile("cp.async.wait_group 2;\n");
        else if (kt == KT - 2) asm volatile("cp.async.wait_group 1;\n");
        else                   asm volatile("cp.async.wait_group 0;\n");
        __syncthreads();

        const uint32_t stA = sb + (kt % STAGES) * STAGE_BYTES;
        const uint32_t stB = stA + A_BYTES;

        uint32_t a[2][4][4], b[2][4][4];

        // prefetch fragments for ks=0
        #pragma unroll
        for (int mi = 0; mi < 4; mi++)
            ldsm4(a[0][mi], stA + aRow[mi] + (uint32_t)((cA ^ a7[mi]) << 4));
        #pragma unroll
        for (int j = 0; j < 4; j++)
            ldsm4(b[0][j], stB + bRow[j] + (uint32_t)((cB ^ b7[j]) << 4));

        // issue next stage fill while fragments are in flight
        if (kt + 3 < KT) {
            const uint32_t so = ((kt + 3) % STAGES) * STAGE_BYTES;
            const int ko = (kt + 3) * BKH;
            #pragma unroll
            for (int j = 0; j < 4; j++) {
                cp_async16(Ad[j]  + so, Ag  + ko + j * 8);
                cp_async16(Bd0[j] + so, Bg0 + ko + j * 8);
                cp_async16(Bd1[j] + so, Bg1 + ko + j * 8);
            }
            asm volatile("cp.async.commit_group;\n");
        }

        #pragma unroll
        for (int ks = 0; ks < 4; ks++) {
            const int cur = ks & 1;
            if (ks < 3) {                      // prefetch ks+1 before mma burst
                const int nxt = cur ^ 1;
                const int ka = 2 * (ks + 1) + cA;
                const int kb = 2 * (ks + 1) + cB;
                #pragma unroll
                for (int mi = 0; mi < 4; mi++)
                    ldsm4(a[nxt][mi], stA + aRow[mi] + (uint32_t)((ka ^ a7[mi]) << 4));
                #pragma unroll
                for (int j = 0; j < 4; j++)
                    ldsm4(b[nxt][j], stB + bRow[j] + (uint32_t)((kb ^ b7[j]) << 4));
            }
            #pragma unroll
            for (int mi = 0; mi < 4; mi++)
                #pragma unroll
                for (int ni = 0; ni < 8; ni++)
                    mma_f16(acc[mi][ni], a[cur][mi], b[cur][ni >> 1][2 * (ni & 1)],
                                                     b[cur][ni >> 1][2 * (ni & 1) + 1]);
        }
    }

    // ---- epilogue ----
    const int g4 = lane >> 2;
    const int t4 = lane & 3;
    #pragma unroll
    for (int mi = 0; mi < 4; mi++) {
        const int row = m0 + wm + mi * 16 + g4;
        #pragma unroll
        for (int ni = 0; ni < 8; ni++) {
            const int col = n0 + wn + ni * 8 + t4 * 2;
            *reinterpret_cast<float2*>(C + (size_t)row * OUTF + col) =
                make_float2(acc[mi][ni][0], acc[mi][ni][1]);
            *reinterpret_cast<float2*>(C + (size_t)(row + 8) * OUTF + col) =
                make_float2(acc[mi][ni][2], acc[mi][ni][3]);
        }
    }
}

// ---------------------------------------------------------------------------
extern "C" void kernel_launch(void* const* d_in, const int* in_sizes, int n_in,
                              void* d_out, int out_size) {
    const float* x    = (const float*)d_in[0];   // (8192, 1024)
    const float* bw   = (const float*)d_in[1];   // (1024, 1024)
    const float* sw   = (const float*)d_in[2];   // (1024, 1024, 8)
    const float* sc   = (const float*)d_in[3];   // (1024, 1024)
    const float* grid = (const float*)d_in[4];   // (1024, 8)
    float* out = (float*)d_out;                  // (8192, 1024)

    (void)in_sizes; (void)n_in; (void)out_size;

    cudaFuncSetAttribute(gemm_f16_kernel,
                         cudaFuncAttributeMaxDynamicSharedMemorySize, SMEM_BYTES);

    prep_w_kernel<<<(OUTF * INF + 255) / 256, 256>>>(bw, sw, sc);
    prep_phi2_kernel<<<512, 256>>>(x, grid);

    dim3 gdim(OUTF / BN, NTOK / BM);             // (4, 64) = 256 CTAs
    gemm_f16_kernel<<<gdim, 256, SMEM_BYTES>>>(out);
}